// round 14
// baseline (speedup 1.0000x reference)
#include <cuda_runtime.h>

#define EMAX 800000
#define NMAX 100000
#define SLOPE_ 0.1f
#define EPS_ 1e-5f

// ---------------- scratch (device globals; no allocation allowed) ----------------
__device__ float g_hA[(size_t)EMAX * 64];   // edge intermediate A
__device__ float g_hB[(size_t)EMAX * 64];   // edge intermediate B
__device__ float g_agg[(size_t)NMAX * 64];  // scatter-sum result
__device__ float g_h2A[(size_t)NMAX * 96];
__device__ float g_h2B[(size_t)NMAX * 96];
__device__ int   g_deg[NMAX];
__device__ float g_sum[6][96];
__device__ float g_sq[6][96];
__device__ float g_Wf[6][96 * 96];          // folded (scale*W) per stage
__device__ float g_cf[6][96];               // folded bias per stage

// ---------------- zero accumulators (must re-zero every graph replay) ----------------
__global__ void k_zero(int n, int nagg) {
    int stride = gridDim.x * blockDim.x;
    int i0 = blockIdx.x * blockDim.x + threadIdx.x;
    for (int i = i0; i < nagg; i += stride) g_agg[i] = 0.f;
    for (int i = i0; i < n; i += stride) g_deg[i] = 0;
    if (i0 < 6 * 96) { (&g_sum[0][0])[i0] = 0.f; (&g_sq[0][0])[i0] = 0.f; }
}

// ---------------- degree count ----------------
__global__ void k_deg(const int* __restrict__ row, int E) {
    int e = blockIdx.x * blockDim.x + threadIdx.x;
    if (e < E) atomicAdd(&g_deg[row[e]], 1);
}

// ---------------- degree-weighted x stats -> stats0 cols [0,32) ----------------
__global__ void k_degw(const float* __restrict__ x, int n) {
    int c = threadIdx.x & 31;
    int g = threadIdx.x >> 5;
    int gpb = blockDim.x >> 5;
    float s = 0.f, q = 0.f;
    for (int r = blockIdx.x * gpb + g; r < n; r += gridDim.x * gpb) {
        float w = (float)g_deg[r];
        float v = x[(size_t)r * 32 + c];
        float wv = w * v;
        s += wv; q += wv * v;
    }
    atomicAdd(&g_sum[0][c], s);
    atomicAdd(&g_sq[0][c], q);
}

// ---------------- generic column stats (sum, sumsq) ----------------
template <int C>
__global__ void k_colstats(const float* __restrict__ src, int rows, int stage, int coff) {
    int gpb = blockDim.x / C;
    int c = threadIdx.x % C;
    int g = threadIdx.x / C;
    if (g >= gpb) return;
    float s = 0.f, q = 0.f;
    for (int r = blockIdx.x * gpb + g; r < rows; r += gridDim.x * gpb) {
        float v = src[(size_t)r * C + c];
        s += v; q += v * v;
    }
    atomicAdd(&g_sum[stage][coff + c], s);
    atomicAdd(&g_sq[stage][coff + c], q);
}

// ---------------- fold BN stats into weights: Wf = scale*W, cf = c + shift@W ----------------
__global__ void k_prep(int stage, float invR,
                       const float* __restrict__ gg, const float* __restrict__ bb,
                       const float* __restrict__ W, const float* __restrict__ c,
                       int IN, int OUT) {
    __shared__ float sSc[96], sSh[96];
    int t = threadIdx.x;
    if (t < IN) {
        float m = g_sum[stage][t] * invR;
        float var = g_sq[stage][t] * invR - m * m;
        float sc = gg[t] * rsqrtf(var + EPS_);
        sSc[t] = sc;
        sSh[t] = bb[t] - m * sc;
    }
    __syncthreads();
    for (int j = t; j < OUT; j += blockDim.x) {
        float a = c[j];
        for (int k = 0; k < IN; k++) {
            float w = W[k * OUT + j];
            g_Wf[stage][k * OUT + j] = sSc[k] * w;
            a += sSh[k] * w;
        }
        g_cf[stage][j] = a;
    }
}

// ================ register-blocked GEMM layer ================
// CTA: 128 rows x OUT cols, thread = 8x8 register tile. 16*(OUT/8) threads.
// MODE: 0 = plain src[IN], 1 = gather x[rowp[e]](32) || src(32), 2 = x[r](32) || src[r](64)
// SMODE: 0 = no stats, 1 = shfl-reduced (OUT==64 only), 2 = direct atomics
template <int IN, int OUT, int MODE, bool LRELU, int SMODE, bool SCATTER>
__global__ __launch_bounds__(16 * (OUT / 8)) void k_rb(
    const float* __restrict__ src, const float* __restrict__ x,
    const int* __restrict__ rowp, const int* __restrict__ colp,
    float* __restrict__ dst, int rows, int stage, int ostage) {
    constexpr int T = 16 * (OUT / 8);
    constexpr int LDA = 132;
    extern __shared__ float sm[];
    float* sW = sm;                        // [IN][OUT]
    float* sCF = sm + IN * OUT;            // [OUT] (padded to 4)
    float* sAT = sCF + ((OUT + 3) & ~3);   // [IN][LDA] transposed A tile
    int tid = threadIdx.x;
    int base = blockIdx.x * 128;

    // weights + bias -> smem
    for (int i = tid; i < IN * OUT / 4; i += T)
        ((float4*)sW)[i] = ((const float4*)g_Wf[stage])[i];
    if (tid < OUT) sCF[tid] = g_cf[stage][tid];

    // A tile staging, transposed: thread t owns row t (zero-fill invalid rows)
    if (tid < 128) {
        int r = base + tid;
        bool v = r < rows;
        int rn = (MODE == 1 && v) ? rowp[r] : 0;
#pragma unroll
        for (int c = 0; c < IN; c += 4) {
            float4 t4 = make_float4(0.f, 0.f, 0.f, 0.f);
            if (v) {
                if (MODE == 0) t4 = *(const float4*)(src + (size_t)r * IN + c);
                else if (MODE == 1)
                    t4 = (c < 32) ? *(const float4*)(x + (size_t)rn * 32 + c)
                                  : *(const float4*)(src + (size_t)r * 32 + (c - 32));
                else
                    t4 = (c < 32) ? *(const float4*)(x + (size_t)r * 32 + c)
                                  : *(const float4*)(src + (size_t)r * 64 + (c - 32));
            }
            sAT[(c + 0) * LDA + tid] = t4.x;
            sAT[(c + 1) * LDA + tid] = t4.y;
            sAT[(c + 2) * LDA + tid] = t4.z;
            sAT[(c + 3) * LDA + tid] = t4.w;
        }
    }
    __syncthreads();

    int tc = tid % (OUT / 8), tr = tid / (OUT / 8);
    float acc[8][8];
#pragma unroll
    for (int i = 0; i < 8; i++)
#pragma unroll
        for (int j = 0; j < 8; j++) acc[i][j] = sCF[8 * tc + j];

    const float* pa = sAT + 8 * tr;
    const float* pw = sW + 8 * tc;
#pragma unroll 2
    for (int k = 0; k < IN; k++) {
        float4 a0 = *(const float4*)(pa + k * LDA);
        float4 a1 = *(const float4*)(pa + k * LDA + 4);
        float4 w0 = *(const float4*)(pw + k * OUT);
        float4 w1 = *(const float4*)(pw + k * OUT + 4);
        float a[8] = {a0.x, a0.y, a0.z, a0.w, a1.x, a1.y, a1.z, a1.w};
        float w[8] = {w0.x, w0.y, w0.z, w0.w, w1.x, w1.y, w1.z, w1.w};
#pragma unroll
        for (int i = 0; i < 8; i++)
#pragma unroll
            for (int j = 0; j < 8; j++) acc[i][j] = fmaf(a[i], w[j], acc[i][j]);
    }

    if (LRELU) {
#pragma unroll
        for (int i = 0; i < 8; i++)
#pragma unroll
            for (int j = 0; j < 8; j++)
                acc[i][j] = acc[i][j] > 0.f ? acc[i][j] : SLOPE_ * acc[i][j];
    }

    // ---- output: store or scatter ----
    if (SCATTER) {
#pragma unroll
        for (int i = 0; i < 8; i++) {
            int e = base + 8 * tr + i;
            if (e < rows) {
                float* dp = g_agg + (size_t)colp[e] * 64 + 8 * tc;
                asm volatile("red.global.add.v4.f32 [%0], {%1, %2, %3, %4};"
                             :: "l"(dp), "f"(acc[i][0]), "f"(acc[i][1]),
                                "f"(acc[i][2]), "f"(acc[i][3]) : "memory");
                asm volatile("red.global.add.v4.f32 [%0], {%1, %2, %3, %4};"
                             :: "l"(dp + 4), "f"(acc[i][4]), "f"(acc[i][5]),
                                "f"(acc[i][6]), "f"(acc[i][7]) : "memory");
            }
        }
    } else {
#pragma unroll
        for (int i = 0; i < 8; i++) {
            int r2 = base + 8 * tr + i;
            if (r2 < rows) {
                float* dp = dst + (size_t)r2 * OUT + 8 * tc;
                *(float4*)dp = make_float4(acc[i][0], acc[i][1], acc[i][2], acc[i][3]);
                *(float4*)(dp + 4) = make_float4(acc[i][4], acc[i][5], acc[i][6], acc[i][7]);
            }
        }
    }

    // ---- fused column stats for next stage ----
    if (SMODE == 1) {   // OUT==64: warp covers 32 consecutive rows for each col group
        int lane = tid & 31;
#pragma unroll
        for (int j = 0; j < 8; j++) {
            float s = 0.f, q = 0.f;
#pragma unroll
            for (int i = 0; i < 8; i++) {
                bool v = (base + 8 * tr + i) < rows;
                float val = v ? acc[i][j] : 0.f;
                s += val; q += val * val;
            }
            s += __shfl_xor_sync(0xffffffffu, s, 8);
            q += __shfl_xor_sync(0xffffffffu, q, 8);
            s += __shfl_xor_sync(0xffffffffu, s, 16);
            q += __shfl_xor_sync(0xffffffffu, q, 16);
            if (lane < 8) {
                atomicAdd(&g_sum[ostage][8 * lane + j], s);
                atomicAdd(&g_sq[ostage][8 * lane + j], q);
            }
        }
    } else if (SMODE == 2) {
#pragma unroll
        for (int j = 0; j < 8; j++) {
            float s = 0.f, q = 0.f;
#pragma unroll
            for (int i = 0; i < 8; i++) {
                bool v = (base + 8 * tr + i) < rows;
                float val = v ? acc[i][j] : 0.f;
                s += val; q += val * val;
            }
            atomicAdd(&g_sum[ostage][8 * tc + j], s);
            atomicAdd(&g_sq[ostage][8 * tc + j], q);
        }
    }
}

// ================ scalar path (final small layer) ================
template <int W>
__device__ __forceinline__ void stage_copy(const float* __restrict__ src, int base, int rows,
                                           float* sIn, int stride, int coff) {
    const int total = 128 * (W / 4);
    for (int idx = threadIdx.x; idx < total; idx += blockDim.x) {
        int r = idx / (W / 4);
        int kk = (idx % (W / 4)) * 4;
        if (base + r < rows) {
            float4 v = *(const float4*)(src + (size_t)(base + r) * W + kk);
            float* d = sIn + r * stride + coff + kk;
            d[0] = v.x; d[1] = v.y; d[2] = v.z; d[3] = v.w;
        }
    }
}

template <int IN, int OUT, bool LRELU>
__device__ __forceinline__ void gemm_one(const float* __restrict__ sIn, const float* __restrict__ sW,
                                         const float* __restrict__ cf, float* acc) {
#pragma unroll
    for (int j = 0; j < OUT; j++) acc[j] = __ldg(cf + j);
#pragma unroll 4
    for (int k = 0; k < IN; k++) {
        float v = sIn[k];
#pragma unroll
        for (int j = 0; j < OUT; j++) acc[j] = fmaf(v, sW[k * OUT + j], acc[j]);
    }
    if (LRELU) {
#pragma unroll
        for (int j = 0; j < OUT; j++) acc[j] = acc[j] > 0.f ? acc[j] : SLOPE_ * acc[j];
    }
}

template <int IN, int OUT, bool LRELU>
__global__ __launch_bounds__(128) void k_layer(const float* __restrict__ src, float* __restrict__ dst,
                                               int rows, int stage) {
    extern __shared__ float sm[];
    float* sW = sm;
    float* sIn = sm + IN * OUT;
    for (int i = threadIdx.x; i < IN * OUT / 4; i += 128)
        ((float4*)sW)[i] = ((const float4*)g_Wf[stage])[i];
    int base = blockIdx.x * 128;
    stage_copy<IN>(src, base, rows, sIn, IN + 1, 0);
    __syncthreads();
    int r = base + threadIdx.x;
    if (r >= rows) return;
    float acc[OUT];
    gemm_one<IN, OUT, LRELU>(sIn + threadIdx.x * (IN + 1), sW, g_cf[stage], acc);
    float* d = dst + (size_t)r * OUT;
#pragma unroll
    for (int j = 0; j < OUT; j += 4)
        *(float4*)(d + j) = make_float4(acc[j], acc[j + 1], acc[j + 2], acc[j + 3]);
}

// ---------------- launcher ----------------
extern "C" void kernel_launch(void* const* d_in, const int* in_sizes, int n_in,
                              void* d_out, int out_size) {
    (void)n_in; (void)out_size;
    const float* x  = (const float*)d_in[0];
    const int*   ei = (const int*)d_in[1];
    const float* ea = (const float*)d_in[2];
    const float* m1g1 = (const float*)d_in[5],  *m1b1 = (const float*)d_in[6];
    const float* m1w1 = (const float*)d_in[7],  *m1c1 = (const float*)d_in[8];
    const float* m1g2 = (const float*)d_in[9],  *m1b2 = (const float*)d_in[10];
    const float* m1w2 = (const float*)d_in[11], *m1c2 = (const float*)d_in[12];
    const float* m1g3 = (const float*)d_in[13], *m1b3 = (const float*)d_in[14];
    const float* m1w3 = (const float*)d_in[15], *m1c3 = (const float*)d_in[16];
    const float* m2g1 = (const float*)d_in[17], *m2b1 = (const float*)d_in[18];
    const float* m2w1 = (const float*)d_in[19], *m2c1 = (const float*)d_in[20];
    const float* m2g2 = (const float*)d_in[21], *m2b2 = (const float*)d_in[22];
    const float* m2w2 = (const float*)d_in[23], *m2c2 = (const float*)d_in[24];
    const float* m2g3 = (const float*)d_in[25], *m2b3 = (const float*)d_in[26];
    const float* m2w3 = (const float*)d_in[27], *m2c3 = (const float*)d_in[28];

    int N = in_sizes[0] / 32;
    int E = in_sizes[2] / 32;
    const int* rowp = ei;
    const int* colp = ei + E;

    float *hA, *hB, *aggp, *h2A, *h2B;
    cudaGetSymbolAddress((void**)&hA, g_hA);
    cudaGetSymbolAddress((void**)&hB, g_hB);
    cudaGetSymbolAddress((void**)&aggp, g_agg);
    cudaGetSymbolAddress((void**)&h2A, g_h2A);
    cudaGetSymbolAddress((void**)&h2B, g_h2B);

    const int SMRB64 = (64 * 64 + 64 + 64 * 132) * 4;   // 50432 B
    const int SMRB96 = (96 * 96 + 96 + 96 * 132) * 4;   // 87936 B
    const int SM96_32 = (96 * 32 + 128 * 97) * 4;       // 61952 B
    cudaFuncSetAttribute(k_rb<64, 64, 1, true, 1, false>, cudaFuncAttributeMaxDynamicSharedMemorySize, SMRB64);
    cudaFuncSetAttribute(k_rb<64, 64, 0, true, 1, false>, cudaFuncAttributeMaxDynamicSharedMemorySize, SMRB64);
    cudaFuncSetAttribute(k_rb<64, 64, 0, false, 0, true>, cudaFuncAttributeMaxDynamicSharedMemorySize, SMRB64);
    cudaFuncSetAttribute(k_rb<96, 96, 2, true, 2, false>, cudaFuncAttributeMaxDynamicSharedMemorySize, SMRB96);
    cudaFuncSetAttribute(k_rb<96, 96, 0, true, 2, false>, cudaFuncAttributeMaxDynamicSharedMemorySize, SMRB96);
    cudaFuncSetAttribute(k_layer<96, 32, false>, cudaFuncAttributeMaxDynamicSharedMemorySize, SM96_32);

    int ebl = (E + 127) / 128;
    int nbl = (N + 127) / 128;

    k_zero<<<2048, 256>>>(N, N * 64);
    // stats of h0 = [x[row] | edge_attr] (degree trick for the x half)
    k_colstats<32><<<512, 256>>>(ea, E, 0, 32);
    k_deg<<<(E + 255) / 256, 256>>>(rowp, E);
    k_degw<<<1024, 256>>>(x, N);
    k_prep<<<1, 128>>>(0, 1.0f / E, m1g1, m1b1, m1w1, m1c1, 64, 64);
    // edge layer 1: gather + GEMM + lrelu + fused stats(hA)
    k_rb<64, 64, 1, true, 1, false><<<ebl, 128, SMRB64>>>(ea, x, rowp, nullptr, hA, E, 0, 1);

    k_prep<<<1, 128>>>(1, 1.0f / E, m1g2, m1b2, m1w2, m1c2, 64, 64);
    // edge layer 2 + fused stats(hB)
    k_rb<64, 64, 0, true, 1, false><<<ebl, 128, SMRB64>>>(hA, nullptr, nullptr, nullptr, hB, E, 1, 2);

    k_prep<<<1, 128>>>(2, 1.0f / E, m1g3, m1b3, m1w3, m1c3, 64, 64);
    // edge layer 3 + scatter-sum
    k_rb<64, 64, 0, false, 0, true><<<ebl, 128, SMRB64>>>(hB, nullptr, nullptr, colp, nullptr, E, 2, 0);

    // stats of h2 = [x | agg]
    k_colstats<32><<<256, 256>>>(x, N, 3, 0);
    k_colstats<64><<<256, 256>>>(aggp, N, 3, 32);
    k_prep<<<1, 128>>>(3, 1.0f / N, m2g1, m2b1, m2w1, m2c1, 96, 96);
    // node layer 1: concat(x, agg) + GEMM + lrelu + fused stats(h2A)
    k_rb<96, 96, 2, true, 2, false><<<nbl, 192, SMRB96>>>(aggp, x, nullptr, nullptr, h2A, N, 3, 4);

    k_prep<<<1, 128>>>(4, 1.0f / N, m2g2, m2b2, m2w2, m2c2, 96, 96);
    // node layer 2 + fused stats(h2B)
    k_rb<96, 96, 0, true, 2, false><<<nbl, 192, SMRB96>>>(h2A, nullptr, nullptr, nullptr, h2B, N, 4, 5);

    k_prep<<<1, 128>>>(5, 1.0f / N, m2g3, m2b3, m2w3, m2c3, 96, 32);
    k_layer<96, 32, false><<<nbl, 128, SM96_32>>>(h2B, (float*)d_out, N, 5);
}

// round 15
// speedup vs baseline: 2.4972x; 2.4972x over previous
#include <cuda_runtime.h>

#define EMAX 800000
#define NMAX 100000
#define SLOPE_ 0.1f
#define EPS_ 1e-5f

// ---------------- scratch (device globals; no allocation allowed) ----------------
__device__ float g_hA[(size_t)EMAX * 64];   // edge intermediate A
__device__ float g_hB[(size_t)EMAX * 64];   // edge intermediate B
__device__ float g_agg[(size_t)NMAX * 64];  // scatter-sum result
__device__ float g_h2A[(size_t)NMAX * 96];
__device__ float g_h2B[(size_t)NMAX * 96];
__device__ int   g_deg[NMAX];
__device__ float g_sum[6][96];
__device__ float g_sq[6][96];
__device__ float g_Wf[6][96 * 96];          // folded (scale*W) per stage
__device__ float g_cf[6][96];               // folded bias per stage

// ---------------- merged prologue stats: ea col-stats + deg count + x col-stats ----------------
// blocks [0,512): ea stats -> stage0 cols [32,64)
// blocks [512,768): x stats -> stage3 cols [0,32)
// blocks [768,1792): degree count
__global__ void k_edgestats(const float* __restrict__ ea, const float* __restrict__ x,
                            const int* __restrict__ row, int E, int N) {
    int b = blockIdx.x;
    if (b < 768) {
        const float* src = (b < 512) ? ea : x;
        int rows = (b < 512) ? E : N;
        int stage = (b < 512) ? 0 : 3;
        int coff = (b < 512) ? 32 : 0;
        int nb = (b < 512) ? 512 : 256;
        int bb = (b < 512) ? b : b - 512;
        int c = threadIdx.x & 31;
        int g = threadIdx.x >> 5;
        int gpb = blockDim.x >> 5;
        float s = 0.f, q = 0.f;
        for (int r = bb * gpb + g; r < rows; r += nb * gpb) {
            float v = src[(size_t)r * 32 + c];
            s += v; q += v * v;
        }
        atomicAdd(&g_sum[stage][coff + c], s);
        atomicAdd(&g_sq[stage][coff + c], q);
    } else {
        int i = (b - 768) * blockDim.x + threadIdx.x;
        int stride = 1024 * blockDim.x;
        for (int e = i; e < E; e += stride) atomicAdd(&g_deg[row[e]], 1);
    }
}

// ---------------- degree-weighted x stats -> stats0 cols [0,32) ----------------
__global__ void k_degw(const float* __restrict__ x, int n) {
    int c = threadIdx.x & 31;
    int g = threadIdx.x >> 5;
    int gpb = blockDim.x >> 5;
    float s = 0.f, q = 0.f;
    for (int r = blockIdx.x * gpb + g; r < n; r += gridDim.x * gpb) {
        float w = (float)g_deg[r];
        float v = x[(size_t)r * 32 + c];
        float wv = w * v;
        s += wv; q += wv * v;
    }
    atomicAdd(&g_sum[0][c], s);
    atomicAdd(&g_sq[0][c], q);
}

// ---------------- generic column stats (sum, sumsq) ----------------
template <int C>
__global__ void k_colstats(const float* __restrict__ src, int rows, int stage, int coff) {
    int gpb = blockDim.x / C;
    int c = threadIdx.x % C;
    int g = threadIdx.x / C;
    if (g >= gpb) return;
    float s = 0.f, q = 0.f;
    for (int r = blockIdx.x * gpb + g; r < rows; r += gridDim.x * gpb) {
        float v = src[(size_t)r * C + c];
        s += v; q += v * v;
    }
    atomicAdd(&g_sum[stage][coff + c], s);
    atomicAdd(&g_sq[stage][coff + c], q);
}

// ---------------- fold BN stats into weights: Wf = scale*W, cf = c + shift@W ----------------
__global__ void k_prep(int stage, float invR,
                       const float* __restrict__ gg, const float* __restrict__ bb,
                       const float* __restrict__ W, const float* __restrict__ c,
                       int IN, int OUT) {
    __shared__ float sSc[96], sSh[96];
    int t = threadIdx.x;
    if (t < IN) {
        float m = g_sum[stage][t] * invR;
        float var = g_sq[stage][t] * invR - m * m;
        float sc = gg[t] * rsqrtf(var + EPS_);
        sSc[t] = sc;
        sSh[t] = bb[t] - m * sc;
    }
    __syncthreads();
    for (int j = t; j < OUT; j += blockDim.x) {
        float a = c[j];
        for (int k = 0; k < IN; k++) {
            float w = W[k * OUT + j];
            g_Wf[stage][k * OUT + j] = sSc[k] * w;
            a += sSh[k] * w;
        }
        g_cf[stage][j] = a;
    }
}

// ---------------- staging helper: copy [base,base+128) rows of width W into padded smem ----------------
template <int W>
__device__ __forceinline__ void stage_copy(const float* __restrict__ src, int base, int rows,
                                           float* sIn, int stride, int coff) {
    const int total = 128 * (W / 4);
    for (int idx = threadIdx.x; idx < total; idx += blockDim.x) {
        int r = idx / (W / 4);
        int kk = (idx % (W / 4)) * 4;
        if (base + r < rows) {
            float4 v = *(const float4*)(src + (size_t)(base + r) * W + kk);
            float* d = sIn + r * stride + coff + kk;
            d[0] = v.x; d[1] = v.y; d[2] = v.z; d[3] = v.w;
        }
    }
}

// ---------------- per-row GEMM core (R4-proven): acc = cf + in @ Wf, optional LReLU ----------------
template <int IN, int OUT, bool LRELU>
__device__ __forceinline__ void gemm_one(const float* __restrict__ sIn, const float* __restrict__ sW,
                                         const float* __restrict__ cf, float* acc) {
#pragma unroll
    for (int j = 0; j < OUT; j++) acc[j] = __ldg(cf + j);
#pragma unroll 4
    for (int k = 0; k < IN; k++) {
        float v = sIn[k];
#pragma unroll
        for (int j = 0; j < OUT; j++) acc[j] = fmaf(v, sW[k * OUT + j], acc[j]);
    }
    if (LRELU) {
#pragma unroll
        for (int j = 0; j < OUT; j++) acc[j] = acc[j] > 0.f ? acc[j] : SLOPE_ * acc[j];
    }
}

// ---------------- fused in-block column stats over smem tile ----------------
template <int C>
__device__ __forceinline__ void block_stats(const float* __restrict__ sOut, int stride,
                                            int nvalid, int ostage) {
    int t = threadIdx.x;
    if (C == 64) {
        int c = t & 63;
        int half = t >> 6;
        int r0 = half * 64;
        int r1 = min(nvalid, r0 + 64);
        float s = 0.f, q = 0.f;
        for (int r = r0; r < r1; r++) {
            float v = sOut[r * stride + c];
            s += v; q += v * v;
        }
        if (r1 > r0) {
            atomicAdd(&g_sum[ostage][c], s);
            atomicAdd(&g_sq[ostage][c], q);
        }
    } else {
        if (t < C) {
            float s = 0.f, q = 0.f;
            for (int r = 0; r < nvalid; r++) {
                float v = sOut[r * stride + t];
                s += v; q += v * v;
            }
            atomicAdd(&g_sum[ostage][t], s);
            atomicAdd(&g_sq[ostage][t], q);
        }
    }
}

// ---------------- layer 1 of edge MLP: gather x[row] || edge_attr, 64->64, LReLU, +stats ----------------
__global__ __launch_bounds__(128) void k_edge1(const float* __restrict__ x, const int* __restrict__ row,
                                               const float* __restrict__ ea, float* __restrict__ dst,
                                               int E, int stage, int ostage) {
    extern __shared__ float sm[];
    float* sW = sm;              // 64*64
    float* sIn = sm + 64 * 64;   // 128*65
    for (int i = threadIdx.x; i < 64 * 64 / 4; i += 128)
        ((float4*)sW)[i] = ((const float4*)g_Wf[stage])[i];
    int base = blockIdx.x * 128;
    stage_copy<32>(ea, base, E, sIn, 65, 32);
    int e = base + threadIdx.x;
    if (e < E) {
        int rn = row[e];
        const float4* xr = (const float4*)(x + (size_t)rn * 32);
        float* d = sIn + threadIdx.x * 65;
#pragma unroll
        for (int k = 0; k < 8; k++) {
            float4 v = xr[k];
            d[4 * k] = v.x; d[4 * k + 1] = v.y; d[4 * k + 2] = v.z; d[4 * k + 3] = v.w;
        }
    }
    __syncthreads();
    float acc[64];
    if (e < E) {
        gemm_one<64, 64, true>(sIn + threadIdx.x * 65, sW, g_cf[stage], acc);
        float* d = dst + (size_t)e * 64;
#pragma unroll
        for (int j = 0; j < 64; j += 4)
            *(float4*)(d + j) = make_float4(acc[j], acc[j + 1], acc[j + 2], acc[j + 3]);
        float* so = sIn + threadIdx.x * 65;  // own row only: no cross-thread hazard
#pragma unroll
        for (int j = 0; j < 64; j++) so[j] = acc[j];
    }
    __syncthreads();
    block_stats<64>(sIn, 65, min(128, E - base), ostage);
}

// ---------------- generic dense layer, optional fused stats ----------------
template <int IN, int OUT, bool LRELU, bool STATS>
__global__ __launch_bounds__(128) void k_layer(const float* __restrict__ src, float* __restrict__ dst,
                                               int rows, int stage, int ostage) {
    extern __shared__ float sm[];
    float* sW = sm;               // IN*OUT
    float* sIn = sm + IN * OUT;   // 128*(IN+1)
    for (int i = threadIdx.x; i < IN * OUT / 4; i += 128)
        ((float4*)sW)[i] = ((const float4*)g_Wf[stage])[i];
    int base = blockIdx.x * 128;
    stage_copy<IN>(src, base, rows, sIn, IN + 1, 0);
    __syncthreads();
    int r = base + threadIdx.x;
    float acc[OUT];
    if (r < rows) {
        gemm_one<IN, OUT, LRELU>(sIn + threadIdx.x * (IN + 1), sW, g_cf[stage], acc);
        float* d = dst + (size_t)r * OUT;
#pragma unroll
        for (int j = 0; j < OUT; j += 4)
            *(float4*)(d + j) = make_float4(acc[j], acc[j + 1], acc[j + 2], acc[j + 3]);
        if (STATS) {
            float* so = sIn + threadIdx.x * (IN + 1);
#pragma unroll
            for (int j = 0; j < OUT; j++) so[j] = acc[j];
        }
    }
    if (STATS) {
        __syncthreads();
        block_stats<OUT>(sIn, IN + 1, min(128, rows - base), ostage);
    }
}

// ---------------- edge MLP layer 3 + vectorized scatter-sum to g_agg ----------------
__global__ __launch_bounds__(128) void k_scatter(const float* __restrict__ src, const int* __restrict__ col,
                                                 int rows, int stage) {
    extern __shared__ float sm[];
    float* sW = sm;
    float* sIn = sm + 64 * 64;
    for (int i = threadIdx.x; i < 64 * 64 / 4; i += 128)
        ((float4*)sW)[i] = ((const float4*)g_Wf[stage])[i];
    int base = blockIdx.x * 128;
    stage_copy<64>(src, base, rows, sIn, 65, 0);
    __syncthreads();
    int e = base + threadIdx.x;
    if (e >= rows) return;
    float acc[64];
    gemm_one<64, 64, false>(sIn + threadIdx.x * 65, sW, g_cf[stage], acc);
    float* d = g_agg + (size_t)col[e] * 64;
#pragma unroll
    for (int j = 0; j < 64; j += 4) {
        asm volatile("red.global.add.v4.f32 [%0], {%1, %2, %3, %4};"
                     :: "l"(d + j), "f"(acc[j]), "f"(acc[j + 1]), "f"(acc[j + 2]), "f"(acc[j + 3])
                     : "memory");
    }
}

// ---------------- node MLP layer 1: concat(x, agg) -> 96, LReLU, +stats ----------------
__global__ __launch_bounds__(128) void k_node1(const float* __restrict__ x, float* __restrict__ dst,
                                               int n, int stage, int ostage) {
    extern __shared__ float sm[];
    float* sW = sm;               // 96*96
    float* sIn = sm + 96 * 96;    // 128*97
    for (int i = threadIdx.x; i < 96 * 96 / 4; i += 128)
        ((float4*)sW)[i] = ((const float4*)g_Wf[stage])[i];
    int base = blockIdx.x * 128;
    stage_copy<32>(x, base, n, sIn, 97, 0);
    stage_copy<64>(g_agg, base, n, sIn, 97, 32);
    __syncthreads();
    int r = base + threadIdx.x;
    float acc[96];
    if (r < n) {
        gemm_one<96, 96, true>(sIn + threadIdx.x * 97, sW, g_cf[stage], acc);
        float* d = dst + (size_t)r * 96;
#pragma unroll
        for (int j = 0; j < 96; j += 4)
            *(float4*)(d + j) = make_float4(acc[j], acc[j + 1], acc[j + 2], acc[j + 3]);
        float* so = sIn + threadIdx.x * 97;
#pragma unroll
        for (int j = 0; j < 96; j++) so[j] = acc[j];
    }
    __syncthreads();
    block_stats<96>(sIn, 97, min(128, n - base), ostage);
}

// ---------------- launcher ----------------
extern "C" void kernel_launch(void* const* d_in, const int* in_sizes, int n_in,
                              void* d_out, int out_size) {
    (void)n_in; (void)out_size;
    const float* x  = (const float*)d_in[0];
    const int*   ei = (const int*)d_in[1];
    const float* ea = (const float*)d_in[2];
    const float* m1g1 = (const float*)d_in[5],  *m1b1 = (const float*)d_in[6];
    const float* m1w1 = (const float*)d_in[7],  *m1c1 = (const float*)d_in[8];
    const float* m1g2 = (const float*)d_in[9],  *m1b2 = (const float*)d_in[10];
    const float* m1w2 = (const float*)d_in[11], *m1c2 = (const float*)d_in[12];
    const float* m1g3 = (const float*)d_in[13], *m1b3 = (const float*)d_in[14];
    const float* m1w3 = (const float*)d_in[15], *m1c3 = (const float*)d_in[16];
    const float* m2g1 = (const float*)d_in[17], *m2b1 = (const float*)d_in[18];
    const float* m2w1 = (const float*)d_in[19], *m2c1 = (const float*)d_in[20];
    const float* m2g2 = (const float*)d_in[21], *m2b2 = (const float*)d_in[22];
    const float* m2w2 = (const float*)d_in[23], *m2c2 = (const float*)d_in[24];
    const float* m2g3 = (const float*)d_in[25], *m2b3 = (const float*)d_in[26];
    const float* m2w3 = (const float*)d_in[27], *m2c3 = (const float*)d_in[28];

    int N = in_sizes[0] / 32;
    int E = in_sizes[2] / 32;
    const int* rowp = ei;
    const int* colp = ei + E;

    float *hA, *hB, *aggp, *h2A, *h2B;
    int* degp;
    float *sump, *sqp;
    cudaGetSymbolAddress((void**)&hA, g_hA);
    cudaGetSymbolAddress((void**)&hB, g_hB);
    cudaGetSymbolAddress((void**)&aggp, g_agg);
    cudaGetSymbolAddress((void**)&h2A, g_h2A);
    cudaGetSymbolAddress((void**)&h2B, g_h2B);
    cudaGetSymbolAddress((void**)&degp, g_deg);
    cudaGetSymbolAddress((void**)&sump, g_sum);
    cudaGetSymbolAddress((void**)&sqp, g_sq);

    const int SM64    = (64 * 64 + 128 * 65) * 4;   // 49664 B
    const int SM96    = (96 * 96 + 128 * 97) * 4;   // 86528 B
    const int SM96_32 = (96 * 32 + 128 * 97) * 4;   // 61952 B
    cudaFuncSetAttribute(k_edge1, cudaFuncAttributeMaxDynamicSharedMemorySize, SM64);
    cudaFuncSetAttribute(k_layer<64, 64, true, true>, cudaFuncAttributeMaxDynamicSharedMemorySize, SM64);
    cudaFuncSetAttribute(k_scatter, cudaFuncAttributeMaxDynamicSharedMemorySize, SM64);
    cudaFuncSetAttribute(k_node1, cudaFuncAttributeMaxDynamicSharedMemorySize, SM96);
    cudaFuncSetAttribute(k_layer<96, 96, true, true>, cudaFuncAttributeMaxDynamicSharedMemorySize, SM96);
    cudaFuncSetAttribute(k_layer<96, 32, false, false>, cudaFuncAttributeMaxDynamicSharedMemorySize, SM96_32);

    int ebl = (E + 127) / 128;
    int nbl = (N + 127) / 128;

    // zeroing via memsets (not kernel launches -> keeps k_edge1 in ncu's profiled slot)
    cudaMemsetAsync(aggp, 0, (size_t)N * 64 * sizeof(float), 0);
    cudaMemsetAsync(degp, 0, (size_t)N * sizeof(int), 0);
    cudaMemsetAsync(sump, 0, 6 * 96 * sizeof(float), 0);
    cudaMemsetAsync(sqp, 0, 6 * 96 * sizeof(float), 0);

    // [0] merged: ea stats (stage0 cols 32-63) + x stats (stage3 cols 0-31) + degree count
    k_edgestats<<<1792, 256>>>(ea, x, rowp, E, N);
    // [1] degree-weighted x stats -> stage0 cols 0-31
    k_degw<<<1024, 256>>>(x, N);
    // [2] fold stage 0
    k_prep<<<1, 128>>>(0, 1.0f / E, m1g1, m1b1, m1w1, m1c1, 64, 64);
    // [3] edge layer 1 (gather + GEMM + lrelu + fused stats->1)  <- ncu profiled slot
    k_edge1<<<ebl, 128, SM64>>>(x, rowp, ea, hA, E, 0, 1);

    k_prep<<<1, 128>>>(1, 1.0f / E, m1g2, m1b2, m1w2, m1c2, 64, 64);
    k_layer<64, 64, true, true><<<ebl, 128, SM64>>>(hA, hB, E, 1, 2);

    k_prep<<<1, 128>>>(2, 1.0f / E, m1g3, m1b3, m1w3, m1c3, 64, 64);
    k_scatter<<<ebl, 128, SM64>>>(hB, colp, E, 2);

    // agg stats -> stage3 cols 32-95
    k_colstats<64><<<256, 256>>>(aggp, N, 3, 32);
    k_prep<<<1, 128>>>(3, 1.0f / N, m2g1, m2b1, m2w1, m2c1, 96, 96);
    k_node1<<<nbl, 128, SM96>>>(x, h2A, N, 3, 4);

    k_prep<<<1, 128>>>(4, 1.0f / N, m2g2, m2b2, m2w2, m2c2, 96, 96);
    k_layer<96, 96, true, true><<<nbl, 128, SM96>>>(h2A, h2B, N, 4, 5);

    k_prep<<<1, 128>>>(5, 1.0f / N, m2g3, m2b3, m2w3, m2c3, 96, 32);
    k_layer<96, 32, false, false><<<nbl, 128, SM96_32>>>(h2B, (float*)d_out, N, 5, 0);
}